// round 15
// baseline (speedup 1.0000x reference)
#include <cuda_runtime.h>
#include <cuda_bf16.h>
#include <math.h>
#include <stdint.h>

#define N 6144
#define D 128
#define INV_TAU 10.0f
#define NB (2 * N)
#define JSPLIT 24
#define TILES_PER 8    // 24*8*64 = 12288 columns

// ---------------- device scratch ----------------
__device__ float g_Fn[N * D];
__device__ float g_Mn[N * D];
__device__ float g_Pn[N * D];
__device__ __nv_bfloat16 g_Abf[N * D];
__device__ __nv_bfloat16 g_Bbf[NB * D];
__device__ float g_repr[2][N * D];
__device__ float g_rowsum[2][N];
__device__ float g_pos[2][N];
__device__ float g_sumall[2][N];
__device__ float g_weights[N * 2];
__device__ float g_loss_acc;

// ---------------- PTX helpers ----------------
__device__ __forceinline__ uint32_t s2u(const void* p) {
    uint32_t a;
    asm("{ .reg .u64 t; cvta.to.shared.u64 t, %1; cvt.u32.u64 %0, t; }" : "=r"(a) : "l"(p));
    return a;
}
__device__ __forceinline__ void cp16(uint32_t dst, const void* src) {
    asm volatile("cp.async.cg.shared.global [%0], [%1], 16;" :: "r"(dst), "l"(src));
}
#define CP_COMMIT() asm volatile("cp.async.commit_group;")
__device__ __forceinline__ void ldsm4(uint32_t* r, uint32_t addr) {
    asm volatile("ldmatrix.sync.aligned.m8n8.x4.shared.b16 {%0,%1,%2,%3}, [%4];"
                 : "=r"(r[0]), "=r"(r[1]), "=r"(r[2]), "=r"(r[3]) : "r"(addr));
}
__device__ __forceinline__ void mma_bf16(float* d, const uint32_t* a, uint32_t b0, uint32_t b1) {
    asm volatile(
        "mma.sync.aligned.m16n8k16.row.col.f32.bf16.bf16.f32 "
        "{%0,%1,%2,%3}, {%4,%5,%6,%7}, {%8,%9}, {%0,%1,%2,%3};"
        : "+f"(d[0]), "+f"(d[1]), "+f"(d[2]), "+f"(d[3])
        : "r"(a[0]), "r"(a[1]), "r"(a[2]), "r"(a[3]), "r"(b0), "r"(b1));
}

// SMEM tiles (stride 272 B = 128 data + 16 pad -> conflict-free ldmatrix)
#define TSTRIDE 272
#define A_TILE_BYTES (128 * TSTRIDE)   // 34816
#define B_TILE_BYTES (64 * TSTRIDE)    // 17408
static constexpr int OFF_A = 0;
static constexpr int OFF_B = A_TILE_BYTES;
static constexpr int SIMTC_SMEM = A_TILE_BYTES + 2 * B_TILE_BYTES;  // 69632

// ---------------- K1: normalize + bf16 cast (+ fused accumulator zeroing) ----
__global__ void k_normalize(const float* __restrict__ embF,
                            const float* __restrict__ embM,
                            const float* __restrict__ embP) {
    int i = blockIdx.x;
    int which = blockIdx.y;
    const float* src = (which == 0) ? embF : (which == 1) ? embM : embP;
    float* dst = (which == 0) ? g_Fn : (which == 1) ? g_Mn : g_Pn;
    int t = threadIdx.x;  // 128
    if (which == 0 && t == 0) {
        g_sumall[0][i] = 0.0f;
        g_sumall[1][i] = 0.0f;
        if (i == 0) g_loss_acc = 0.0f;
    }
    float v = src[(size_t)i * D + t];
    __shared__ float red[128];
    red[t] = v * v;
    __syncthreads();
#pragma unroll
    for (int s = 64; s > 0; s >>= 1) {
        if (t < s) red[t] += red[t + s];
        __syncthreads();
    }
    float norm = fmaxf(sqrtf(red[0]), 1e-12f);
    float nv = v / norm;
    dst[(size_t)i * D + t] = nv;
    __nv_bfloat16 h = __float2bfloat16(nv);
    if (which == 0) g_Abf[i * D + t] = h;
    else g_Bbf[((which == 1) ? i : (N + i)) * D + t] = h;
}

// ---------------- K2: adjacency scan ({0,1} values: integer nonzero test) ----
#define MAXNZ 768
__global__ __launch_bounds__(128) void k_repr_pos(
    const float* __restrict__ FM_adj, const float* __restrict__ FP_adj,
    const float* __restrict__ embM, const float* __restrict__ embP) {
    int i = blockIdx.x;
    int w = blockIdx.y;
    const float* adj = (w == 0) ? FM_adj : FP_adj;
    const float* emb = (w == 0) ? embM : embP;
    const float* nrm = (w == 0) ? g_Mn : g_Pn;
    int t = threadIdx.x;
    int lane = t & 31;

    __shared__ int s_idx[MAXNZ];
    __shared__ int s_cnt;
    __shared__ float s_pos;
    __shared__ float s_F[D];

    if (t == 0) { s_cnt = 0; s_pos = 0.0f; }
    s_F[t] = g_Fn[(size_t)i * D + t];
    __syncthreads();

    const uint4* arow = (const uint4*)(adj + (size_t)i * N);
#pragma unroll 4
    for (int c = t; c < N / 4; c += 128) {
        uint4 u = __ldcs(&arow[c]);
        if (((u.x | u.y) | (u.z | u.w)) != 0u) {  // rare (~2%)
            int nh = (u.x != 0u) + (u.y != 0u) + (u.z != 0u) + (u.w != 0u);
            int p = atomicAdd(&s_cnt, nh);
            if (u.x != 0u) { if (p < MAXNZ) s_idx[p] = 4 * c + 0; ++p; }
            if (u.y != 0u) { if (p < MAXNZ) s_idx[p] = 4 * c + 1; ++p; }
            if (u.z != 0u) { if (p < MAXNZ) s_idx[p] = 4 * c + 2; ++p; }
            if (u.w != 0u) { if (p < MAXNZ) s_idx[p] = 4 * c + 3; ++p; }
        }
    }
    __syncthreads();

    int total = s_cnt;
    int cnt = min(total, MAXNZ);
    float denom = fmaxf((float)total, 1.0f);

    float a0 = 0, a1 = 0, a2 = 0, a3 = 0;
    int e = 0;
    for (; e + 4 <= cnt; e += 4) {
        a0 += emb[(size_t)s_idx[e + 0] * D + t];
        a1 += emb[(size_t)s_idx[e + 1] * D + t];
        a2 += emb[(size_t)s_idx[e + 2] * D + t];
        a3 += emb[(size_t)s_idx[e + 3] * D + t];
    }
    for (; e < cnt; ++e) a0 += emb[(size_t)s_idx[e] * D + t];
    g_repr[w][(size_t)i * D + t] = ((a0 + a1) + (a2 + a3)) / denom;
    if (t == 0) g_rowsum[w][i] = (float)total;

    int warp = t >> 5;
    float lp = 0.0f;
    for (int q = warp; q < cnt; q += 4) {
        int j = s_idx[q];
        const float* nr = nrm + (size_t)j * D;
        float pd = s_F[lane] * nr[lane]
                 + s_F[lane + 32] * nr[lane + 32]
                 + s_F[lane + 64] * nr[lane + 64]
                 + s_F[lane + 96] * nr[lane + 96];
#pragma unroll
        for (int o = 16; o; o >>= 1) pd += __shfl_xor_sync(0xffffffffu, pd, o);
        if (lane == 0) lp += __expf(pd * INV_TAU);
    }
    if (lane == 0) atomicAdd(&s_pos, lp);
    __syncthreads();
    if (t == 0) g_pos[w][i] = s_pos;
}

// ---------------- K3: bf16 HMMA sim row sums (BN=64) ----------------
__device__ __forceinline__ void load_tileA(uint32_t dst, const __nv_bfloat16* src,
                                           int row0, int tid) {
#pragma unroll
    for (int p = 0; p < 8; ++p) {
        int idx = tid + (p << 8);
        int r = idx >> 4, c = idx & 15;
        cp16(dst + r * TSTRIDE + c * 16, src + (size_t)(row0 + r) * D + c * 8);
    }
}
__device__ __forceinline__ void load_tileB(uint32_t dst, const __nv_bfloat16* src,
                                           int row0, int tid) {
#pragma unroll
    for (int p = 0; p < 4; ++p) {
        int idx = tid + (p << 8);
        int r = idx >> 4, c = idx & 15;
        cp16(dst + r * TSTRIDE + c * 16, src + (size_t)(row0 + r) * D + c * 8);
    }
}

__global__ __launch_bounds__(256, 2) void k_simsum_mma() {
    extern __shared__ __align__(16) char dsm[];
    const uint32_t smb = s2u(dsm);
    const int tid = threadIdx.x;
    const int wid = tid >> 5;
    const int lane = tid & 31;
    const int wm = (wid & 3) * 32;
    const int wn = (wid >> 2) * 32;
    const int i0 = blockIdx.x * 128;
    const int tbase = blockIdx.y * TILES_PER;
    const int tgt = (blockIdx.y < JSPLIT / 2) ? 0 : 1;

    const uint32_t aoff = (uint32_t)(lane & 15) * TSTRIDE + (uint32_t)(lane >> 4) * 16;
    const uint32_t boff = (uint32_t)(((lane >> 3) & 1) * 8 + (lane & 7)) * TSTRIDE
                        + (uint32_t)(lane >> 4) * 16;

    load_tileA(smb + OFF_A, g_Abf, i0, tid);
    load_tileB(smb + OFF_B, g_Bbf, tbase * 64, tid);
    CP_COMMIT();
    load_tileB(smb + OFF_B + B_TILE_BYTES, g_Bbf, (tbase + 1) * 64, tid);
    CP_COMMIT();

    float rsum[2][2] = {{0, 0}, {0, 0}};

    for (int t = 0; t < TILES_PER; ++t) {
        const int buf = t & 1;
        asm volatile("cp.async.wait_group 1;");
        __syncthreads();

        const uint32_t bb = smb + OFF_B + buf * B_TILE_BYTES;

        float acc[2][4][4];
#pragma unroll
        for (int f = 0; f < 2; ++f)
#pragma unroll
            for (int n = 0; n < 4; ++n)
#pragma unroll
                for (int r = 0; r < 4; ++r) acc[f][n][r] = 0.0f;

#pragma unroll
        for (int ks = 0; ks < 8; ++ks) {
            uint32_t ah[2][4];
#pragma unroll
            for (int f = 0; f < 2; ++f)
                ldsm4(ah[f], smb + OFF_A + (wm + f * 16) * TSTRIDE + ks * 32 + aoff);
#pragma unroll
            for (int g = 0; g < 2; ++g) {
                uint32_t bh[4];
                ldsm4(bh, bb + (wn + g * 16) * TSTRIDE + ks * 32 + boff);
#pragma unroll
                for (int f = 0; f < 2; ++f) {
                    mma_bf16(acc[f][2 * g], ah[f], bh[0], bh[2]);
                    mma_bf16(acc[f][2 * g + 1], ah[f], bh[1], bh[3]);
                }
            }
        }

        __syncthreads();
        if (t + 2 < TILES_PER)
            load_tileB(smb + OFF_B + buf * B_TILE_BYTES, g_Bbf, (tbase + t + 2) * 64, tid);
        CP_COMMIT();

#pragma unroll
        for (int f = 0; f < 2; ++f) {
            float e0 = 0.0f, e1 = 0.0f;
#pragma unroll
            for (int n = 0; n < 4; ++n) {
                e0 += __expf(acc[f][n][0] * INV_TAU) + __expf(acc[f][n][1] * INV_TAU);
                e1 += __expf(acc[f][n][2] * INV_TAU) + __expf(acc[f][n][3] * INV_TAU);
            }
            rsum[f][0] += e0;
            rsum[f][1] += e1;
        }
    }

#pragma unroll
    for (int f = 0; f < 2; ++f)
#pragma unroll
        for (int r = 0; r < 2; ++r) {
            float v = rsum[f][r];
            v += __shfl_xor_sync(0xffffffffu, v, 1);
            v += __shfl_xor_sync(0xffffffffu, v, 2);
            if ((lane & 3) == 0) {
                int row = i0 + wm + f * 16 + (lane >> 2) + r * 8;
                atomicAdd(&g_sumall[tgt][row], v);
            }
        }
}

// ---------------- K4: MLP + softmax (high occupancy, W1 from L2) ----------------
#define MLP_ROWS 16
#define FSTR 257
#define MLP_SMEM ((MLP_ROWS * FSTR) * (int)sizeof(float))  // 16448
__global__ __launch_bounds__(256) void k_mlp(const float* __restrict__ W1,
                                             const float* __restrict__ b1,
                                             const float* __restrict__ W2,
                                             const float* __restrict__ b2,
                                             float* __restrict__ out_weights) {
    extern __shared__ float feats[];  // [16][FSTR]

    const int tid = threadIdx.x;
    const int lane = tid & 31;
    const int wp = tid >> 5;
    const int i0 = blockIdx.x * MLP_ROWS;

#pragma unroll
    for (int p = 0; p < MLP_ROWS; ++p) {
        int s = tid + p * 256;
        int r = s >> 8, k = s & 255;
        feats[r * FSTR + k] = (k < 128) ? g_repr[0][(size_t)(i0 + r) * D + k]
                                        : g_repr[1][(size_t)(i0 + r) * D + (k - 128)];
    }
    __syncthreads();

    const int c4 = lane;
    const float4* W1v = (const float4*)W1;  // [256][32] float4
    const float4 b1v = ((const float4*)b1)[c4];
    const float4 w2a = ((const float4*)W2)[2 * c4];
    const float4 w2b = ((const float4*)W2)[2 * c4 + 1];
    const int r0 = wp * 2;  // 8 warps * 2 rows = 16

    float acc[2][4];
#pragma unroll
    for (int r = 0; r < 2; ++r)
#pragma unroll
        for (int q = 0; q < 4; ++q) acc[r][q] = 0.0f;

    float4 wv = __ldg(&W1v[c4]);
#pragma unroll 4
    for (int k = 0; k < 256; ++k) {
        float4 nv;
        if (k < 255) nv = __ldg(&W1v[(k + 1) * 32 + c4]);
#pragma unroll
        for (int r = 0; r < 2; ++r) {
            float f = feats[(r0 + r) * FSTR + k];
            acc[r][0] = fmaf(f, wv.x, acc[r][0]);
            acc[r][1] = fmaf(f, wv.y, acc[r][1]);
            acc[r][2] = fmaf(f, wv.z, acc[r][2]);
            acc[r][3] = fmaf(f, wv.w, acc[r][3]);
        }
        wv = nv;
    }

#pragma unroll
    for (int r = 0; r < 2; ++r) {
        float h0 = fmaxf(acc[r][0] + b1v.x, 0.0f);
        float h1 = fmaxf(acc[r][1] + b1v.y, 0.0f);
        float h2 = fmaxf(acc[r][2] + b1v.z, 0.0f);
        float h3 = fmaxf(acc[r][3] + b1v.w, 0.0f);
        float p0 = h0 * w2a.x + h1 * w2a.z + h2 * w2b.x + h3 * w2b.z;
        float p1 = h0 * w2a.y + h1 * w2a.w + h2 * w2b.y + h3 * w2b.w;
#pragma unroll
        for (int o = 16; o; o >>= 1) {
            p0 += __shfl_xor_sync(0xffffffffu, p0, o);
            p1 += __shfl_xor_sync(0xffffffffu, p1, o);
        }
        if (lane == 0) {
            int row = i0 + r0 + r;
            float o0 = p0 + b2[0];
            float o1 = p1 + b2[1];
            float mx = fmaxf(o0, o1);
            float e0 = expf(o0 - mx), e1 = expf(o1 - mx);
            float inv = 1.0f / (e0 + e1);
            float w0 = e0 * inv, w1 = e1 * inv;
            g_weights[2 * row] = w0;
            g_weights[2 * row + 1] = w1;
            out_weights[2 * row] = w0;
            out_weights[2 * row + 1] = w1;
        }
    }
}

// ---------------- K5: loss ----------------
__global__ __launch_bounds__(256) void k_loss() {
    int idx = blockIdx.x * blockDim.x + threadIdx.x;
    int stride = gridDim.x * blockDim.x;
    float term = 0.0f;
    for (int i = idx; i < N; i += stride) {
        float w0 = g_weights[2 * i], w1 = g_weights[2 * i + 1];
        float pm = g_pos[0][i], pp = g_pos[1][i];
        float sm = g_sumall[0][i], sp = g_sumall[1][i];
        float wpv = w0 * pm + w1 * pp;
        float wn = w0 * (sm - pm) + w1 * (sp - pp);
        float nei = fmaxf(g_rowsum[0][i] + g_rowsum[1][i], 1.0f);
        float ratio = wpv / (wpv + wn) / nei;
        ratio = fmaxf(ratio, 1e-10f);
        term += -logf(ratio);
    }
    __shared__ float red[256];
    red[threadIdx.x] = term;
    __syncthreads();
#pragma unroll
    for (int s = 128; s > 0; s >>= 1) {
        if (threadIdx.x < s) red[threadIdx.x] += red[threadIdx.x + s];
        __syncthreads();
    }
    if (threadIdx.x == 0) atomicAdd(&g_loss_acc, red[0]);
}

__global__ void k_finalize(float* __restrict__ out) {
    out[0] = g_loss_acc / (float)N;
}

// ---------------- launch (fork-join overlap; side stream = high priority) ----
extern "C" void kernel_launch(void* const* d_in, const int* in_sizes, int n_in,
                              void* d_out, int out_size) {
    const float* embF = (const float*)d_in[0];
    const float* embM = (const float*)d_in[1];
    const float* embP = (const float*)d_in[2];
    const float* FM_adj = (const float*)d_in[3];
    const float* FP_adj = (const float*)d_in[4];
    const float* W1 = (const float*)d_in[5];
    const float* b1 = (const float*)d_in[6];
    const float* W2 = (const float*)d_in[7];
    const float* b2 = (const float*)d_in[8];
    float* out = (float*)d_out;

    static cudaStream_t s1 = nullptr;
    static cudaEvent_t evA = nullptr, evB = nullptr;
    static bool attr_set = false;
    if (!attr_set) {
        int lo, hi;
        cudaDeviceGetStreamPriorityRange(&lo, &hi);
        cudaStreamCreateWithPriority(&s1, cudaStreamNonBlocking, hi);
        cudaEventCreateWithFlags(&evA, cudaEventDisableTiming);
        cudaEventCreateWithFlags(&evB, cudaEventDisableTiming);
        cudaFuncSetAttribute(k_simsum_mma, cudaFuncAttributeMaxDynamicSharedMemorySize, SIMTC_SMEM);
        cudaFuncSetAttribute(k_mlp, cudaFuncAttributeMaxDynamicSharedMemorySize, MLP_SMEM);
        attr_set = true;
    }

    k_normalize<<<dim3(N, 3), 128>>>(embF, embM, embP);
    cudaEventRecord(evA, 0);

    // main branch: tensor-core sim sums
    k_simsum_mma<<<dim3(N / 128, JSPLIT), 256, SIMTC_SMEM>>>();

    // side branch (critical path): adjacency scan + MLP on high-priority stream
    cudaStreamWaitEvent(s1, evA, 0);
    k_repr_pos<<<dim3(N, 2), 128, 0, s1>>>(FM_adj, FP_adj, embM, embP);
    k_mlp<<<N / MLP_ROWS, 256, MLP_SMEM, s1>>>(W1, b1, W2, b2, out + 1);
    cudaEventRecord(evB, s1);

    cudaStreamWaitEvent(0, evB, 0);
    k_loss<<<24, 256>>>();
    k_finalize<<<1, 1>>>(out);
}

// round 16
// speedup vs baseline: 1.1047x; 1.1047x over previous
#include <cuda_runtime.h>
#include <cuda_bf16.h>
#include <math.h>
#include <stdint.h>

#define N 6144
#define D 128
#define INV_TAU 10.0f
#define NB (2 * N)
#define JSPLIT 12
#define TILES_PER 16   // 12*16*64 = 12288 columns

// ---------------- device scratch ----------------
__device__ float g_Fn[N * D];
__device__ float g_Mn[N * D];
__device__ float g_Pn[N * D];
__device__ __nv_bfloat16 g_Abf[N * D];
__device__ __nv_bfloat16 g_Bbf[NB * D];
__device__ float g_repr[2][N * D];
__device__ float g_rowsum[2][N];
__device__ float g_pos[2][N];
__device__ float g_sumall[2][N];
__device__ float g_weights[N * 2];
__device__ float g_loss_acc;

// ---------------- PTX helpers ----------------
__device__ __forceinline__ uint32_t s2u(const void* p) {
    uint32_t a;
    asm("{ .reg .u64 t; cvta.to.shared.u64 t, %1; cvt.u32.u64 %0, t; }" : "=r"(a) : "l"(p));
    return a;
}
__device__ __forceinline__ void cp16(uint32_t dst, const void* src) {
    asm volatile("cp.async.cg.shared.global [%0], [%1], 16;" :: "r"(dst), "l"(src));
}
#define CP_COMMIT() asm volatile("cp.async.commit_group;")
__device__ __forceinline__ void ldsm4(uint32_t* r, uint32_t addr) {
    asm volatile("ldmatrix.sync.aligned.m8n8.x4.shared.b16 {%0,%1,%2,%3}, [%4];"
                 : "=r"(r[0]), "=r"(r[1]), "=r"(r[2]), "=r"(r[3]) : "r"(addr));
}
__device__ __forceinline__ void mma_bf16(float* d, const uint32_t* a, uint32_t b0, uint32_t b1) {
    asm volatile(
        "mma.sync.aligned.m16n8k16.row.col.f32.bf16.bf16.f32 "
        "{%0,%1,%2,%3}, {%4,%5,%6,%7}, {%8,%9}, {%0,%1,%2,%3};"
        : "+f"(d[0]), "+f"(d[1]), "+f"(d[2]), "+f"(d[3])
        : "r"(a[0]), "r"(a[1]), "r"(a[2]), "r"(a[3]), "r"(b0), "r"(b1));
}

// SMEM tiles (stride 272 B = 128 data + 16 pad -> conflict-free ldmatrix)
#define TSTRIDE 272
#define A_TILE_BYTES (128 * TSTRIDE)   // 34816
#define B_TILE_BYTES (64 * TSTRIDE)    // 17408
static constexpr int OFF_A = 0;
static constexpr int OFF_B = A_TILE_BYTES;
static constexpr int SIMTC_SMEM = A_TILE_BYTES + 2 * B_TILE_BYTES;  // 69632

// ---------------- K1: normalize + bf16 cast (+ fused accumulator zeroing) ----
__global__ void k_normalize(const float* __restrict__ embF,
                            const float* __restrict__ embM,
                            const float* __restrict__ embP) {
    int i = blockIdx.x;
    int which = blockIdx.y;
    const float* src = (which == 0) ? embF : (which == 1) ? embM : embP;
    float* dst = (which == 0) ? g_Fn : (which == 1) ? g_Mn : g_Pn;
    int t = threadIdx.x;  // 128
    if (which == 0 && t == 0) {
        g_sumall[0][i] = 0.0f;
        g_sumall[1][i] = 0.0f;
        if (i == 0) g_loss_acc = 0.0f;
    }
    float v = src[(size_t)i * D + t];
    __shared__ float red[128];
    red[t] = v * v;
    __syncthreads();
#pragma unroll
    for (int s = 64; s > 0; s >>= 1) {
        if (t < s) red[t] += red[t + s];
        __syncthreads();
    }
    float norm = fmaxf(sqrtf(red[0]), 1e-12f);
    float nv = v / norm;
    dst[(size_t)i * D + t] = nv;
    __nv_bfloat16 h = __float2bfloat16(nv);
    if (which == 0) g_Abf[i * D + t] = h;
    else g_Bbf[((which == 1) ? i : (N + i)) * D + t] = h;
}

// ---------------- K2: adjacency scan ({0,1} values: integer nonzero test) ----
#define MAXNZ 768
__global__ __launch_bounds__(128) void k_repr_pos(
    const float* __restrict__ FM_adj, const float* __restrict__ FP_adj,
    const float* __restrict__ embM, const float* __restrict__ embP) {
    int i = blockIdx.x;
    int w = blockIdx.y;
    const float* adj = (w == 0) ? FM_adj : FP_adj;
    const float* emb = (w == 0) ? embM : embP;
    const float* nrm = (w == 0) ? g_Mn : g_Pn;
    int t = threadIdx.x;
    int lane = t & 31;

    __shared__ int s_idx[MAXNZ];
    __shared__ int s_cnt;
    __shared__ float s_pos;
    __shared__ float s_F[D];

    if (t == 0) { s_cnt = 0; s_pos = 0.0f; }
    s_F[t] = g_Fn[(size_t)i * D + t];
    __syncthreads();

    const uint4* arow = (const uint4*)(adj + (size_t)i * N);
#pragma unroll 4
    for (int c = t; c < N / 4; c += 128) {
        uint4 u = __ldcs(&arow[c]);
        if (((u.x | u.y) | (u.z | u.w)) != 0u) {  // rare (~2%)
            int nh = (u.x != 0u) + (u.y != 0u) + (u.z != 0u) + (u.w != 0u);
            int p = atomicAdd(&s_cnt, nh);
            if (u.x != 0u) { if (p < MAXNZ) s_idx[p] = 4 * c + 0; ++p; }
            if (u.y != 0u) { if (p < MAXNZ) s_idx[p] = 4 * c + 1; ++p; }
            if (u.z != 0u) { if (p < MAXNZ) s_idx[p] = 4 * c + 2; ++p; }
            if (u.w != 0u) { if (p < MAXNZ) s_idx[p] = 4 * c + 3; ++p; }
        }
    }
    __syncthreads();

    int total = s_cnt;
    int cnt = min(total, MAXNZ);
    float denom = fmaxf((float)total, 1.0f);

    float a0 = 0, a1 = 0, a2 = 0, a3 = 0;
    int e = 0;
    for (; e + 4 <= cnt; e += 4) {
        a0 += emb[(size_t)s_idx[e + 0] * D + t];
        a1 += emb[(size_t)s_idx[e + 1] * D + t];
        a2 += emb[(size_t)s_idx[e + 2] * D + t];
        a3 += emb[(size_t)s_idx[e + 3] * D + t];
    }
    for (; e < cnt; ++e) a0 += emb[(size_t)s_idx[e] * D + t];
    g_repr[w][(size_t)i * D + t] = ((a0 + a1) + (a2 + a3)) / denom;
    if (t == 0) g_rowsum[w][i] = (float)total;

    int warp = t >> 5;
    float lp = 0.0f;
    for (int q = warp; q < cnt; q += 4) {
        int j = s_idx[q];
        const float* nr = nrm + (size_t)j * D;
        float pd = s_F[lane] * nr[lane]
                 + s_F[lane + 32] * nr[lane + 32]
                 + s_F[lane + 64] * nr[lane + 64]
                 + s_F[lane + 96] * nr[lane + 96];
#pragma unroll
        for (int o = 16; o; o >>= 1) pd += __shfl_xor_sync(0xffffffffu, pd, o);
        if (lane == 0) lp += __expf(pd * INV_TAU);
    }
    if (lane == 0) atomicAdd(&s_pos, lp);
    __syncthreads();
    if (t == 0) g_pos[w][i] = s_pos;
}

// ---------------- K3: bf16 HMMA sim row sums (BN=64) ----------------
__device__ __forceinline__ void load_tileA(uint32_t dst, const __nv_bfloat16* src,
                                           int row0, int tid) {
#pragma unroll
    for (int p = 0; p < 8; ++p) {
        int idx = tid + (p << 8);
        int r = idx >> 4, c = idx & 15;
        cp16(dst + r * TSTRIDE + c * 16, src + (size_t)(row0 + r) * D + c * 8);
    }
}
__device__ __forceinline__ void load_tileB(uint32_t dst, const __nv_bfloat16* src,
                                           int row0, int tid) {
#pragma unroll
    for (int p = 0; p < 4; ++p) {
        int idx = tid + (p << 8);
        int r = idx >> 4, c = idx & 15;
        cp16(dst + r * TSTRIDE + c * 16, src + (size_t)(row0 + r) * D + c * 8);
    }
}

__global__ __launch_bounds__(256, 2) void k_simsum_mma() {
    extern __shared__ __align__(16) char dsm[];
    const uint32_t smb = s2u(dsm);
    const int tid = threadIdx.x;
    const int wid = tid >> 5;
    const int lane = tid & 31;
    const int wm = (wid & 3) * 32;
    const int wn = (wid >> 2) * 32;
    const int i0 = blockIdx.x * 128;
    const int tbase = blockIdx.y * TILES_PER;
    const int tgt = (blockIdx.y < JSPLIT / 2) ? 0 : 1;

    const uint32_t aoff = (uint32_t)(lane & 15) * TSTRIDE + (uint32_t)(lane >> 4) * 16;
    const uint32_t boff = (uint32_t)(((lane >> 3) & 1) * 8 + (lane & 7)) * TSTRIDE
                        + (uint32_t)(lane >> 4) * 16;

    load_tileA(smb + OFF_A, g_Abf, i0, tid);
    load_tileB(smb + OFF_B, g_Bbf, tbase * 64, tid);
    CP_COMMIT();
    load_tileB(smb + OFF_B + B_TILE_BYTES, g_Bbf, (tbase + 1) * 64, tid);
    CP_COMMIT();

    float rsum[2][2] = {{0, 0}, {0, 0}};

    for (int t = 0; t < TILES_PER; ++t) {
        const int buf = t & 1;
        asm volatile("cp.async.wait_group 1;");
        __syncthreads();

        const uint32_t bb = smb + OFF_B + buf * B_TILE_BYTES;

        float acc[2][4][4];
#pragma unroll
        for (int f = 0; f < 2; ++f)
#pragma unroll
            for (int n = 0; n < 4; ++n)
#pragma unroll
                for (int r = 0; r < 4; ++r) acc[f][n][r] = 0.0f;

#pragma unroll
        for (int ks = 0; ks < 8; ++ks) {
            uint32_t ah[2][4];
#pragma unroll
            for (int f = 0; f < 2; ++f)
                ldsm4(ah[f], smb + OFF_A + (wm + f * 16) * TSTRIDE + ks * 32 + aoff);
#pragma unroll
            for (int g = 0; g < 2; ++g) {
                uint32_t bh[4];
                ldsm4(bh, bb + (wn + g * 16) * TSTRIDE + ks * 32 + boff);
#pragma unroll
                for (int f = 0; f < 2; ++f) {
                    mma_bf16(acc[f][2 * g], ah[f], bh[0], bh[2]);
                    mma_bf16(acc[f][2 * g + 1], ah[f], bh[1], bh[3]);
                }
            }
        }

        __syncthreads();
        if (t + 2 < TILES_PER)
            load_tileB(smb + OFF_B + buf * B_TILE_BYTES, g_Bbf, (tbase + t + 2) * 64, tid);
        CP_COMMIT();

#pragma unroll
        for (int f = 0; f < 2; ++f) {
            float e0 = 0.0f, e1 = 0.0f;
#pragma unroll
            for (int n = 0; n < 4; ++n) {
                e0 += __expf(acc[f][n][0] * INV_TAU) + __expf(acc[f][n][1] * INV_TAU);
                e1 += __expf(acc[f][n][2] * INV_TAU) + __expf(acc[f][n][3] * INV_TAU);
            }
            rsum[f][0] += e0;
            rsum[f][1] += e1;
        }
    }

#pragma unroll
    for (int f = 0; f < 2; ++f)
#pragma unroll
        for (int r = 0; r < 2; ++r) {
            float v = rsum[f][r];
            v += __shfl_xor_sync(0xffffffffu, v, 1);
            v += __shfl_xor_sync(0xffffffffu, v, 2);
            if ((lane & 3) == 0) {
                int row = i0 + wm + f * 16 + (lane >> 2) + r * 8;
                atomicAdd(&g_sumall[tgt][row], v);
            }
        }
}

// ---------------- K4: MLP + softmax (R14 form: W1 staged, 6 rows/warp) ----------
#define MLP_ROWS 48
#define FSTR 257
#define MLP_SMEM ((256 * 128 + MLP_ROWS * FSTR) * (int)sizeof(float))
__global__ __launch_bounds__(256) void k_mlp(const float* __restrict__ W1,
                                             const float* __restrict__ b1,
                                             const float* __restrict__ W2,
                                             const float* __restrict__ b2,
                                             float* __restrict__ out_weights) {
    extern __shared__ float smf[];
    float* W1s = smf;
    float* feats = smf + 256 * 128;

    const int tid = threadIdx.x;
    const int lane = tid & 31;
    const int wp = tid >> 5;
    const int i0 = blockIdx.x * MLP_ROWS;

#pragma unroll
    for (int p = 0; p < 32; ++p) {
        int s = tid + p * 256;
        ((float4*)W1s)[s] = ((const float4*)W1)[s];
    }
#pragma unroll
    for (int p = 0; p < MLP_ROWS; ++p) {
        int s = tid + p * 256;
        int r = s >> 8, k = s & 255;
        feats[r * FSTR + k] = (k < 128) ? g_repr[0][(size_t)(i0 + r) * D + k]
                                        : g_repr[1][(size_t)(i0 + r) * D + (k - 128)];
    }
    __syncthreads();

    const int c4 = lane;
    const float4 b1v = ((const float4*)b1)[c4];
    const float4 w2a = ((const float4*)W2)[2 * c4];
    const float4 w2b = ((const float4*)W2)[2 * c4 + 1];
    const int r0 = wp * 6;

    float acc[6][4];
#pragma unroll
    for (int r = 0; r < 6; ++r)
#pragma unroll
        for (int q = 0; q < 4; ++q) acc[r][q] = 0.0f;

#pragma unroll 4
    for (int k = 0; k < 256; ++k) {
        float4 wv = *(const float4*)&W1s[k * 128 + 4 * c4];
#pragma unroll
        for (int r = 0; r < 6; ++r) {
            float f = feats[(r0 + r) * FSTR + k];
            acc[r][0] = fmaf(f, wv.x, acc[r][0]);
            acc[r][1] = fmaf(f, wv.y, acc[r][1]);
            acc[r][2] = fmaf(f, wv.z, acc[r][2]);
            acc[r][3] = fmaf(f, wv.w, acc[r][3]);
        }
    }

#pragma unroll
    for (int r = 0; r < 6; ++r) {
        float h0 = fmaxf(acc[r][0] + b1v.x, 0.0f);
        float h1 = fmaxf(acc[r][1] + b1v.y, 0.0f);
        float h2 = fmaxf(acc[r][2] + b1v.z, 0.0f);
        float h3 = fmaxf(acc[r][3] + b1v.w, 0.0f);
        float p0 = h0 * w2a.x + h1 * w2a.z + h2 * w2b.x + h3 * w2b.z;
        float p1 = h0 * w2a.y + h1 * w2a.w + h2 * w2b.y + h3 * w2b.w;
#pragma unroll
        for (int o = 16; o; o >>= 1) {
            p0 += __shfl_xor_sync(0xffffffffu, p0, o);
            p1 += __shfl_xor_sync(0xffffffffu, p1, o);
        }
        if (lane == 0) {
            int row = i0 + r0 + r;
            float o0 = p0 + b2[0];
            float o1 = p1 + b2[1];
            float mx = fmaxf(o0, o1);
            float e0 = expf(o0 - mx), e1 = expf(o1 - mx);
            float inv = 1.0f / (e0 + e1);
            float w0 = e0 * inv, w1 = e1 * inv;
            g_weights[2 * row] = w0;
            g_weights[2 * row + 1] = w1;
            out_weights[2 * row] = w0;
            out_weights[2 * row + 1] = w1;
        }
    }
}

// ---------------- K5: loss ----------------
__global__ __launch_bounds__(256) void k_loss() {
    int idx = blockIdx.x * blockDim.x + threadIdx.x;
    int stride = gridDim.x * blockDim.x;
    float term = 0.0f;
    for (int i = idx; i < N; i += stride) {
        float w0 = g_weights[2 * i], w1 = g_weights[2 * i + 1];
        float pm = g_pos[0][i], pp = g_pos[1][i];
        float sm = g_sumall[0][i], sp = g_sumall[1][i];
        float wpv = w0 * pm + w1 * pp;
        float wn = w0 * (sm - pm) + w1 * (sp - pp);
        float nei = fmaxf(g_rowsum[0][i] + g_rowsum[1][i], 1.0f);
        float ratio = wpv / (wpv + wn) / nei;
        ratio = fmaxf(ratio, 1e-10f);
        term += -logf(ratio);
    }
    __shared__ float red[256];
    red[threadIdx.x] = term;
    __syncthreads();
#pragma unroll
    for (int s = 128; s > 0; s >>= 1) {
        if (threadIdx.x < s) red[threadIdx.x] += red[threadIdx.x + s];
        __syncthreads();
    }
    if (threadIdx.x == 0) atomicAdd(&g_loss_acc, red[0]);
}

__global__ void k_finalize(float* __restrict__ out) {
    out[0] = g_loss_acc / (float)N;
}

// ---------------- launch (fork-join overlap; side stream = high priority) ----
extern "C" void kernel_launch(void* const* d_in, const int* in_sizes, int n_in,
                              void* d_out, int out_size) {
    const float* embF = (const float*)d_in[0];
    const float* embM = (const float*)d_in[1];
    const float* embP = (const float*)d_in[2];
    const float* FM_adj = (const float*)d_in[3];
    const float* FP_adj = (const float*)d_in[4];
    const float* W1 = (const float*)d_in[5];
    const float* b1 = (const float*)d_in[6];
    const float* W2 = (const float*)d_in[7];
    const float* b2 = (const float*)d_in[8];
    float* out = (float*)d_out;

    static cudaStream_t s1 = nullptr;
    static cudaEvent_t evA = nullptr, evB = nullptr;
    static bool attr_set = false;
    if (!attr_set) {
        int lo, hi;
        cudaDeviceGetStreamPriorityRange(&lo, &hi);
        cudaStreamCreateWithPriority(&s1, cudaStreamNonBlocking, hi);
        cudaEventCreateWithFlags(&evA, cudaEventDisableTiming);
        cudaEventCreateWithFlags(&evB, cudaEventDisableTiming);
        cudaFuncSetAttribute(k_simsum_mma, cudaFuncAttributeMaxDynamicSharedMemorySize, SIMTC_SMEM);
        cudaFuncSetAttribute(k_mlp, cudaFuncAttributeMaxDynamicSharedMemorySize, MLP_SMEM);
        attr_set = true;
    }

    k_normalize<<<dim3(N, 3), 128>>>(embF, embM, embP);
    cudaEventRecord(evA, 0);

    // main branch: tensor-core sim sums
    k_simsum_mma<<<dim3(N / 128, JSPLIT), 256, SIMTC_SMEM>>>();

    // side branch (critical path): adjacency scan + MLP on high-priority stream
    cudaStreamWaitEvent(s1, evA, 0);
    k_repr_pos<<<dim3(N, 2), 128, 0, s1>>>(FM_adj, FP_adj, embM, embP);
    k_mlp<<<N / MLP_ROWS, 256, MLP_SMEM, s1>>>(W1, b1, W2, b2, out + 1);
    cudaEventRecord(evB, s1);

    cudaStreamWaitEvent(0, evB, 0);
    k_loss<<<24, 256>>>();
    k_finalize<<<1, 1>>>(out);
}